// round 3
// baseline (speedup 1.0000x reference)
#include <cuda_runtime.h>

#define B_SZ 1024
#define N_SZ 16
#define T_SZ 256
// packed lower-triangular index (compile-time after unroll)
#define TRI(i, j) ((i) * ((i) + 1) / 2 + (j))

__global__ void gll_zero_kernel(float* out) { out[0] = 0.0f; }

__global__ void __launch_bounds__(T_SZ)
gll_kernel(const float* __restrict__ pred,
           const float* __restrict__ targ,
           const float* __restrict__ cov,
           float* __restrict__ out) {
    const int b = blockIdx.x;   // 0..1023
    const int t = threadIdx.x;  // 0..255

    // ---- load lower triangle of Sigma: cov[b, i, j, t], T innermost => coalesced
    float a[N_SZ * (N_SZ + 1) / 2];
    const long cov_base = (long)b * (N_SZ * N_SZ * T_SZ) + t;
#pragma unroll
    for (int i = 0; i < N_SZ; i++) {
#pragma unroll
        for (int j = 0; j <= i; j++) {
            a[TRI(i, j)] = cov[cov_base + (i * N_SZ + j) * T_SZ];
        }
    }

    // ---- diff = pred - target : [B, N, T], coalesced
    float d[N_SZ];
    const long pt_base = (long)b * (N_SZ * T_SZ) + t;
#pragma unroll
    for (int i = 0; i < N_SZ; i++) {
        const long off = pt_base + (long)i * T_SZ;
        d[i] = pred[off] - targ[off];
    }

    // ---- in-place Cholesky (left-looking), store 1/L_jj on the diagonal
    float logdet = 0.0f;
#pragma unroll
    for (int j = 0; j < N_SZ; j++) {
        float s = a[TRI(j, j)];
#pragma unroll
        for (int k = 0; k < j; k++) {
            const float l = a[TRI(j, k)];
            s -= l * l;
        }
        const float dia = sqrtf(s);
        const float inv = 1.0f / dia;
        logdet += __logf(dia);
        a[TRI(j, j)] = inv;
#pragma unroll
        for (int i = j + 1; i < N_SZ; i++) {
            float s2 = a[TRI(i, j)];
#pragma unroll
            for (int k = 0; k < j; k++) {
                s2 -= a[TRI(i, k)] * a[TRI(j, k)];
            }
            a[TRI(i, j)] = s2 * inv;
        }
    }
    logdet *= 2.0f;  // log det(Sigma) = 2 * sum log L_jj

    // ---- forward solve L y = diff; quad = ||y||^2
    float quad = 0.0f;
    float y[N_SZ];
#pragma unroll
    for (int i = 0; i < N_SZ; i++) {
        float s = d[i];
#pragma unroll
        for (int k = 0; k < i; k++) {
            s -= a[TRI(i, k)] * y[k];
        }
        y[i] = s * a[TRI(i, i)];  // diagonal holds 1/L_ii
        quad += y[i] * y[i];
    }

    float val = (quad + logdet) * (1.0f / ((float)B_SZ * (float)T_SZ));

    // ---- block reduction: warp shuffle, then smem across 8 warps
#pragma unroll
    for (int off = 16; off > 0; off >>= 1)
        val += __shfl_xor_sync(0xFFFFFFFFu, val, off);

    __shared__ float warp_sums[T_SZ / 32];
    const int lane = threadIdx.x & 31;
    const int wid  = threadIdx.x >> 5;
    if (lane == 0) warp_sums[wid] = val;
    __syncthreads();

    if (wid == 0) {
        float v = (lane < T_SZ / 32) ? warp_sums[lane] : 0.0f;
#pragma unroll
        for (int off = 4; off > 0; off >>= 1)
            v += __shfl_xor_sync(0xFFFFFFFFu, v, off);
        if (lane == 0) atomicAdd(out, v);
    }
}

extern "C" void kernel_launch(void* const* d_in, const int* in_sizes, int n_in,
                              void* d_out, int out_size) {
    const float* pred = (const float*)d_in[0];
    const float* targ = (const float*)d_in[1];
    const float* cov  = (const float*)d_in[2];
    float* out = (float*)d_out;

    gll_zero_kernel<<<1, 1>>>(out);
    gll_kernel<<<B_SZ, T_SZ>>>(pred, targ, cov, out);
}

// round 4
// speedup vs baseline: 1.4058x; 1.4058x over previous
#include <cuda_runtime.h>

#define B_SZ 1024
#define N_SZ 16
#define T_SZ 256
// packed lower-triangular index (compile-time after unroll)
#define TRI(i, j) ((i) * ((i) + 1) / 2 + (j))

__global__ void gll_zero_kernel(float* out) { out[0] = 0.0f; }

__global__ void __launch_bounds__(T_SZ, 2)
gll_kernel(const float* __restrict__ pred,
           const float* __restrict__ targ,
           const float* __restrict__ cov,
           float* __restrict__ out) {
    const unsigned b = blockIdx.x;   // 0..1023
    const unsigned t = threadIdx.x;  // 0..255

    // ---- load lower triangle of Sigma: cov[b, i, j, t], T innermost => coalesced
    // 32-bit indexing: max offset = 1024*16*16*256 = 67M, fits in uint32.
    float a[N_SZ * (N_SZ + 1) / 2];
    const unsigned cov_base = b * (N_SZ * N_SZ * T_SZ) + t;
#pragma unroll
    for (int i = 0; i < N_SZ; i++) {
#pragma unroll
        for (int j = 0; j <= i; j++) {
            a[TRI(i, j)] = cov[cov_base + (unsigned)((i * N_SZ + j) * T_SZ)];
        }
    }

    // ---- in-place Cholesky (left-looking).
    // Diagonal stores 1/L_jj (via rsqrt). logdet(Sigma) = sum_j log(pivot_j),
    // pivots >= 1 (Sigma = A A^T + I) so the running product stays in
    // [1, ~1e26] -- safe in fp32; one __logf at the end.
    float pivprod = 1.0f;
#pragma unroll
    for (int j = 0; j < N_SZ; j++) {
        float s = a[TRI(j, j)];
#pragma unroll
        for (int k = 0; k < j; k++) {
            const float l = a[TRI(j, k)];
            s -= l * l;
        }
        pivprod *= s;
        const float inv = rsqrtf(s);
        a[TRI(j, j)] = inv;
#pragma unroll
        for (int i = j + 1; i < N_SZ; i++) {
            float s2 = a[TRI(i, j)];
#pragma unroll
            for (int k = 0; k < j; k++) {
                s2 -= a[TRI(i, k)] * a[TRI(j, k)];
            }
            a[TRI(i, j)] = s2 * inv;
        }
    }
    const float logdet = __logf(pivprod);

    // ---- diff = pred - target, loaded AFTER factorization to shrink live range
    float d[N_SZ];
    const unsigned pt_base = b * (N_SZ * T_SZ) + t;
#pragma unroll
    for (int i = 0; i < N_SZ; i++) {
        const unsigned off = pt_base + (unsigned)(i * T_SZ);
        d[i] = pred[off] - targ[off];
    }

    // ---- forward solve L y = diff; quad = ||y||^2  (diagonal holds 1/L_ii)
    float quad = 0.0f;
    float y[N_SZ];
#pragma unroll
    for (int i = 0; i < N_SZ; i++) {
        float s = d[i];
#pragma unroll
        for (int k = 0; k < i; k++) {
            s -= a[TRI(i, k)] * y[k];
        }
        y[i] = s * a[TRI(i, i)];
        quad += y[i] * y[i];
    }

    float val = (quad + logdet) * (1.0f / ((float)B_SZ * (float)T_SZ));

    // ---- block reduction: warp shuffle, then smem across 8 warps
#pragma unroll
    for (int off = 16; off > 0; off >>= 1)
        val += __shfl_xor_sync(0xFFFFFFFFu, val, off);

    __shared__ float warp_sums[T_SZ / 32];
    const int lane = threadIdx.x & 31;
    const int wid  = threadIdx.x >> 5;
    if (lane == 0) warp_sums[wid] = val;
    __syncthreads();

    if (wid == 0) {
        float v = (lane < T_SZ / 32) ? warp_sums[lane] : 0.0f;
#pragma unroll
        for (int off = 4; off > 0; off >>= 1)
            v += __shfl_xor_sync(0xFFFFFFFFu, v, off);
        if (lane == 0) atomicAdd(out, v);
    }
}

extern "C" void kernel_launch(void* const* d_in, const int* in_sizes, int n_in,
                              void* d_out, int out_size) {
    const float* pred = (const float*)d_in[0];
    const float* targ = (const float*)d_in[1];
    const float* cov  = (const float*)d_in[2];
    float* out = (float*)d_out;

    gll_zero_kernel<<<1, 1>>>(out);
    gll_kernel<<<B_SZ, T_SZ>>>(pred, targ, cov, out);
}